// round 14
// baseline (speedup 1.0000x reference)
#include <cuda_runtime.h>
#include <cstdint>

// ERGCN layer:
//   msg[k] = h[src[k]] * weight[rel[k]] + e[k] * attention[rel[k]]   (D=64)
//   out    = h + segment_sum(msg, dst)
//
// Inputs: h[N*64] f32, e[E*64] f32, weight[R*64] f32, attention[R*64] f32,
//         src[E] i32, dst[E] i32, rel[E] i32. Output: [N*64] f32.

#define D 64
#define D4 (D / 4)          // 16 float4 per row
#define TPB 128
#define EPB (TPB / 8)       // 16 edges per block-iteration per stream
#define NBLOCKS (148 * 7)   // one exact wave at 7 CTAs/SM (<=73 regs)

// e stream: bypass L1 allocation (zero reuse; keep tables/h resident in L1).
__device__ __forceinline__ float4 ldg_stream(const float4* p) {
    float4 v;
    asm("ld.global.nc.L1::no_allocate.v4.f32 {%0,%1,%2,%3}, [%4];"
        : "=f"(v.x), "=f"(v.y), "=f"(v.z), "=f"(v.w) : "l"(p));
    return v;
}

__device__ __forceinline__ void red_add_v4(float* o, float4 m) {
    asm volatile("red.global.add.v4.f32 [%0], {%1, %2, %3, %4};"
                 :: "l"(o), "f"(m.x), "f"(m.y), "f"(m.z), "f"(m.w)
                 : "memory");
}

// ---------------------------------------------------------------------------
// Kernel 1: out = h (d_out is poisoned before timing)
// ---------------------------------------------------------------------------
__global__ void init_out_kernel(float4* __restrict__ out,
                                const float4* __restrict__ h,
                                int n4) {
    int i = blockIdx.x * blockDim.x + threadIdx.x;
    if (i < n4) out[i] = h[i];
}

// ---------------------------------------------------------------------------
// Kernel 2: 8 threads/edge, TWO independent edge streams per thread
// (A: [0,EA), B: [EA,E)), each with a distance-1 idx+e software pipeline.
// ~38 outstanding LDGs per warp; 7 CTAs/SM -> ~1060 loads in flight per SM.
// ---------------------------------------------------------------------------
__global__ void __launch_bounds__(TPB, 7)
edge_kernel(const float* __restrict__ h,
            const float* __restrict__ e,
            const float4* __restrict__ w_g,
            const float4* __restrict__ a_g,
            const int* __restrict__ src,
            const int* __restrict__ dst,
            const int* __restrict__ rel,
            float* __restrict__ out,
            int E_, int EA) {
    const int t      = threadIdx.x & 7;           // chunk (t and t+8)
    const int group  = threadIdx.x >> 3;          // edge slot within block
    const int stride = NBLOCKS * EPB;             // slots per stream
    const int slot   = blockIdx.x * EPB + group;  // < stride <= EA always

    // Stream state: k, indices, e prefetch.
    int kA = slot;        // walks [0, EA)
    int kB = EA + slot;   // walks [EA, E)
    bool aA = true, aB = true;

    int sA = __ldg(src + kA), dA = __ldg(dst + kA), rA = __ldg(rel + kA);
    int sB = __ldg(src + kB), dB = __ldg(dst + kB), rB = __ldg(rel + kB);
    float4 evA0 = ldg_stream((const float4*)(e + (size_t)kA * D) + t);
    float4 evA1 = ldg_stream((const float4*)(e + (size_t)kA * D) + t + 8);
    float4 evB0 = ldg_stream((const float4*)(e + (size_t)kB * D) + t);
    float4 evB1 = ldg_stream((const float4*)(e + (size_t)kB * D) + t + 8);

    while (true) {
        // ---- Prefetch next iteration for both streams (independent) ----
        const int knA = kA + stride;
        const int knB = kB + stride;
        const bool mA = knA < EA;
        const bool mB = knB < E_;
        const int kcA = mA ? knA : kA;            // clamp: harmless reload
        const int kcB = mB ? knB : kB;

        const int snA = __ldg(src + kcA);
        const int dnA = __ldg(dst + kcA);
        const int rnA = __ldg(rel + kcA);
        const int snB = __ldg(src + kcB);
        const int dnB = __ldg(dst + kcB);
        const int rnB = __ldg(rel + kcB);
        const float4 enA0 = ldg_stream((const float4*)(e + (size_t)kcA * D) + t);
        const float4 enA1 = ldg_stream((const float4*)(e + (size_t)kcA * D) + t + 8);
        const float4 enB0 = ldg_stream((const float4*)(e + (size_t)kcB * D) + t);
        const float4 enB1 = ldg_stream((const float4*)(e + (size_t)kcB * D) + t + 8);

        // ---- Issue ALL current gathers (indices resolved last iter) ----
        const float4* hpA = (const float4*)(h + (size_t)sA * D) + t;
        const float4* wpA = w_g + rA * D4 + t;
        const float4* apA = a_g + rA * D4 + t;
        const float4* hpB = (const float4*)(h + (size_t)sB * D) + t;
        const float4* wpB = w_g + rB * D4 + t;
        const float4* apB = a_g + rB * D4 + t;

        const float4 hvA0 = __ldg(hpA);
        const float4 hvA1 = __ldg(hpA + 8);
        const float4 hvB0 = __ldg(hpB);
        const float4 hvB1 = __ldg(hpB + 8);
        const float4 wvA0 = __ldg(wpA);
        const float4 wvA1 = __ldg(wpA + 8);
        const float4 avA0 = __ldg(apA);
        const float4 avA1 = __ldg(apA + 8);
        const float4 wvB0 = __ldg(wpB);
        const float4 wvB1 = __ldg(wpB + 8);
        const float4 avB0 = __ldg(apB);
        const float4 avB1 = __ldg(apB + 8);

        // ---- Stream A: compute + scatter ----
        if (aA) {
            float4 m0, m1;
            m0.x = fmaf(hvA0.x, wvA0.x, evA0.x * avA0.x);
            m0.y = fmaf(hvA0.y, wvA0.y, evA0.y * avA0.y);
            m0.z = fmaf(hvA0.z, wvA0.z, evA0.z * avA0.z);
            m0.w = fmaf(hvA0.w, wvA0.w, evA0.w * avA0.w);
            m1.x = fmaf(hvA1.x, wvA1.x, evA1.x * avA1.x);
            m1.y = fmaf(hvA1.y, wvA1.y, evA1.y * avA1.y);
            m1.z = fmaf(hvA1.z, wvA1.z, evA1.z * avA1.z);
            m1.w = fmaf(hvA1.w, wvA1.w, evA1.w * avA1.w);
            float* o = out + (size_t)dA * D + t * 4;
            red_add_v4(o, m0);
            red_add_v4(o + 32, m1);
        }

        // ---- Stream B: compute + scatter ----
        if (aB) {
            float4 m0, m1;
            m0.x = fmaf(hvB0.x, wvB0.x, evB0.x * avB0.x);
            m0.y = fmaf(hvB0.y, wvB0.y, evB0.y * avB0.y);
            m0.z = fmaf(hvB0.z, wvB0.z, evB0.z * avB0.z);
            m0.w = fmaf(hvB0.w, wvB0.w, evB0.w * avB0.w);
            m1.x = fmaf(hvB1.x, wvB1.x, evB1.x * avB1.x);
            m1.y = fmaf(hvB1.y, wvB1.y, evB1.y * avB1.y);
            m1.z = fmaf(hvB1.z, wvB1.z, evB1.z * avB1.z);
            m1.w = fmaf(hvB1.w, wvB1.w, evB1.w * avB1.w);
            float* o = out + (size_t)dB * D + t * 4;
            red_add_v4(o, m0);
            red_add_v4(o + 32, m1);
        }

        if (!mA && !mB) break;

        // ---- Rotate pipeline state ----
        kA = knA; aA = mA; sA = snA; dA = dnA; rA = rnA; evA0 = enA0; evA1 = enA1;
        kB = knB; aB = mB; sB = snB; dB = dnB; rB = rnB; evB0 = enB0; evB1 = enB1;
    }
}

extern "C" void kernel_launch(void* const* d_in, const int* in_sizes, int n_in,
                              void* d_out, int out_size) {
    const float* h   = (const float*)d_in[0];
    const float* e   = (const float*)d_in[1];
    const float* wgt = (const float*)d_in[2];
    const float* att = (const float*)d_in[3];
    const int*   src = (const int*)d_in[4];
    const int*   dst = (const int*)d_in[5];
    const int*   rel = (const int*)d_in[6];
    float*       out = (float*)d_out;

    const int ND = in_sizes[0];      // N * 64
    const int E_ = in_sizes[4];      // edge count
    const int EA = (E_ + 1) / 2;     // stream A takes [0, EA), B takes [EA, E)

    // out = h
    {
        int n4 = ND / 4;
        init_out_kernel<<<(n4 + 255) / 256, 256>>>(
            (float4*)out, (const float4*)h, n4);
    }

    // persistent 2-stream pipelined edge kernel, one wave at 7 CTAs/SM
    edge_kernel<<<NBLOCKS, TPB>>>(h, e, (const float4*)wgt,
                                  (const float4*)att,
                                  src, dst, rel, out, E_, EA);
}